// round 6
// baseline (speedup 1.0000x reference)
#include <cuda_runtime.h>

#define M_TOTAL 2048
#define IN_DIM  4096
#define OUT_DIM 4096
#define NB      16
#define RANK    16
#define BLK     256
#define NQ      8      // split-K eighths in kernelA
#define KA      32     // p's per piece

typedef unsigned long long u64;

// Scratch (__device__ globals per allocation rules)
__device__ float g_T[NQ * M_TOTAL * NB * RANK];   // [qt][m][i][r]  16 MB (L2-resident)
__device__ float g_Z[NB * M_TOTAL * RANK];        // [o][m][r]      2 MB
__device__ float g_rsp[M_TOTAL * NB * NQ];        // [m][i*8+qt]    1 MB

// ---------- f32x2 packed helpers ----------
__device__ __forceinline__ u64 pack2(float lo, float hi) {
    u64 r; asm("mov.b64 %0, {%1, %2};" : "=l"(r) : "f"(lo), "f"(hi)); return r;
}
__device__ __forceinline__ void unpack2(u64 p, float& lo, float& hi) {
    asm("mov.b64 {%0, %1}, %2;" : "=f"(lo), "=f"(hi) : "l"(p));
}
__device__ __forceinline__ void ffma2(u64& d, u64 a, u64 b) {
    asm("fma.rn.f32x2 %0, %1, %2, %0;" : "+l"(d) : "l"(a), "l"(b));
}
__device__ __forceinline__ void fadd2(u64& d, u64 a) {
    asm("add.rn.f32x2 %0, %0, %1;" : "+l"(d) : "l"(a));
}

// ================= Kernel A =================
// Thread tile: 2 rows x all 16 r, f32x2 paired over p. 0.25 wavefronts/FFMA2.
#define ROWS_A  512
#define XSTR    36     // 32 + 4 pad floats; conflict-free for 8-lane LDS.128 phases

__global__ void __launch_bounds__(256, 2)
kernelA(const float* __restrict__ x, const float* __restrict__ Vt)
{
    extern __shared__ float sm[];
    float* xs   = sm;                          // 512*36*4 = 73,728 B
    u64*   vts2 = (u64*)(sm + ROWS_A * XSTR);  // [p2][r] (Vt[2p2][r],Vt[2p2+1][r]) 2 KB

    const int ib   = blockIdx.x >> 3;
    const int qt   = blockIdx.x & 7;
    const int row0 = blockIdx.y * ROWS_A;
    const int tid  = threadIdx.x;

    // Vt piece interleaved into p-pairs: thread -> (p2 = tid>>4, r = tid&15)
    {
        int p2 = tid >> 4, r = tid & 15;
        const float* vg = Vt + ((size_t)ib * BLK + qt * KA + 2 * p2) * RANK + r;
        vts2[p2 * 16 + r] = pack2(vg[0], vg[RANK]);
    }

    // x tile: 512 rows x 32 cols
    const float4* xg4 = (const float4*)x;
    #pragma unroll
    for (int idx = tid; idx < ROWS_A * 8; idx += 256) {
        int m  = idx >> 3;
        int c4 = idx & 7;
        ((float4*)(xs + m * XSTR))[c4] =
            xg4[(size_t)(row0 + m) * (IN_DIM / 4) + ib * 64 + qt * 8 + c4];
    }
    __syncthreads();

    const float* xr0 = xs + tid * XSTR;            // row tid
    const float* xr1 = xs + (tid + 256) * XSTR;    // row tid+256

    u64 accA[16], accB[16];
    #pragma unroll
    for (int r = 0; r < 16; ++r) { accA[r] = 0ULL; accB[r] = 0ULL; }
    u64 rsA = 0ULL, rsB = 0ULL;                    // inline rowsum (pairwise)

    #pragma unroll
    for (int p4 = 0; p4 < 8; ++p4) {
        ulonglong2 xa = *(const ulonglong2*)(xr0 + p4 * 4);   // (p0,p1),(p2,p3)
        ulonglong2 xb = *(const ulonglong2*)(xr1 + p4 * 4);
        fadd2(rsA, xa.x); fadd2(rsA, xa.y);
        fadd2(rsB, xb.x); fadd2(rsB, xb.y);

        const u64* v0 = vts2 + (2 * p4) * 16;       // p2 = 2p4
        #pragma unroll
        for (int rr = 0; rr < 16; rr += 4) {
            ulonglong2 va = *(const ulonglong2*)(v0 + rr);
            ulonglong2 vb = *(const ulonglong2*)(v0 + rr + 2);
            ffma2(accA[rr],   xa.x, va.x); ffma2(accA[rr+1], xa.x, va.y);
            ffma2(accA[rr+2], xa.x, vb.x); ffma2(accA[rr+3], xa.x, vb.y);
            ffma2(accB[rr],   xb.x, va.x); ffma2(accB[rr+1], xb.x, va.y);
            ffma2(accB[rr+2], xb.x, vb.x); ffma2(accB[rr+3], xb.x, vb.y);
        }
        const u64* v1 = vts2 + (2 * p4 + 1) * 16;   // p2 = 2p4+1
        #pragma unroll
        for (int rr = 0; rr < 16; rr += 4) {
            ulonglong2 va = *(const ulonglong2*)(v1 + rr);
            ulonglong2 vb = *(const ulonglong2*)(v1 + rr + 2);
            ffma2(accA[rr],   xa.y, va.x); ffma2(accA[rr+1], xa.y, va.y);
            ffma2(accA[rr+2], xa.y, vb.x); ffma2(accA[rr+3], xa.y, vb.y);
            ffma2(accB[rr],   xb.y, va.x); ffma2(accB[rr+1], xb.y, va.y);
            ffma2(accB[rr+2], xb.y, vb.x); ffma2(accB[rr+3], xb.y, vb.y);
        }
    }

    // Combine even/odd-p partials; store T ([qt][m][i][r]) and rowsum partials
    float* gTq = g_T + (size_t)qt * (M_TOTAL * NB * RANK);
    {
        float* dst = gTq + (size_t)(row0 + tid) * (NB * RANK) + ib * RANK;
        #pragma unroll
        for (int rr = 0; rr < 16; rr += 4) {
            float4 t; float lo, hi;
            unpack2(accA[rr],   lo, hi); t.x = lo + hi;
            unpack2(accA[rr+1], lo, hi); t.y = lo + hi;
            unpack2(accA[rr+2], lo, hi); t.z = lo + hi;
            unpack2(accA[rr+3], lo, hi); t.w = lo + hi;
            *(float4*)(dst + rr) = t;
        }
        dst = gTq + (size_t)(row0 + tid + 256) * (NB * RANK) + ib * RANK;
        #pragma unroll
        for (int rr = 0; rr < 16; rr += 4) {
            float4 t; float lo, hi;
            unpack2(accB[rr],   lo, hi); t.x = lo + hi;
            unpack2(accB[rr+1], lo, hi); t.y = lo + hi;
            unpack2(accB[rr+2], lo, hi); t.z = lo + hi;
            unpack2(accB[rr+3], lo, hi); t.w = lo + hi;
            *(float4*)(dst + rr) = t;
        }
        float lo, hi;
        unpack2(rsA, lo, hi);
        g_rsp[(size_t)(row0 + tid) * (NB * NQ) + ib * NQ + qt] = lo + hi;
        unpack2(rsB, lo, hi);
        g_rsp[(size_t)(row0 + tid + 256) * (NB * NQ) + ib * NQ + qt] = lo + hi;
    }
}

// ================= Kernel Z: Z[o][m][r] = sum_i T[m,i,r]*S[o,i,r] =================
#define ROWS_Z  8
#define TSTR    260

__global__ void __launch_bounds__(256)
kernelZ(const float* __restrict__ S)
{
    __shared__ float Ts[ROWS_Z * TSTR];    // 8.3 KB
    __shared__ float Ss[NB * NB * RANK];   // 16 KB

    const int row0 = blockIdx.x * ROWS_Z;
    const int tid  = threadIdx.x;

    #pragma unroll
    for (int i = tid; i < 1024; i += 256) ((float4*)Ss)[i] = ((const float4*)S)[i];

    // Sum 8 split-K pieces; contiguous per (qt,row)
    const float4* gT4 = (const float4*)g_T;
    const size_t  qs  = (size_t)M_TOTAL * 64;   // float4 per piece
    #pragma unroll
    for (int idx = tid; idx < ROWS_Z * 64; idx += 256) {
        int m  = idx >> 6;
        int c4 = idx & 63;
        size_t base = (size_t)(row0 + m) * 64 + c4;
        float4 a = gT4[base];
        #pragma unroll
        for (int q = 1; q < NQ; ++q) {
            float4 b = gT4[base + q * qs];
            a.x += b.x; a.y += b.y; a.z += b.z; a.w += b.w;
        }
        ((float4*)(Ts + m * TSTR))[c4] = a;
    }
    __syncthreads();

    const int m  = tid >> 5;          // 0..7
    const int r  = (tid >> 1) & 15;
    const int oh = tid & 1;           // o-half

    float t[NB];
    #pragma unroll
    for (int i = 0; i < NB; ++i) t[i] = Ts[m * TSTR + i * 16 + r];

    #pragma unroll
    for (int oo = 0; oo < 8; ++oo) {
        int o = oh * 8 + oo;
        float z = 0.f;
        #pragma unroll
        for (int i = 0; i < NB; ++i) z = fmaf(t[i], Ss[o * 256 + i * 16 + r], z);
        g_Z[((size_t)o * M_TOTAL + row0 + m) * RANK + r] = z;
    }
}

// ================= Kernel B: out = Z @ U + (1+rowsum)*bias =================
#define ROWS_B  32
#define ZS2     34      // u64 stride (even -> 16B-aligned ull2 loads)

__global__ void __launch_bounds__(256)
kernelB(const float* __restrict__ U, const float* __restrict__ bias,
        float* __restrict__ out)
{
    __shared__ float Us[RANK * BLK];       // 16 KB
    __shared__ u64   Zt2[RANK * ZS2];      // (z,z) duplicated pairs, [r][m]
    __shared__ float rs[ROWS_B];

    const int o    = blockIdx.x;
    const int row0 = blockIdx.y * ROWS_B;
    const int tid  = threadIdx.x;

    const float4* Ug4 = (const float4*)(U + (size_t)o * (RANK * BLK));
    #pragma unroll
    for (int i = tid; i < 1024; i += 256) ((float4*)Us)[i] = Ug4[i];

    if (tid < 128) {
        int m  = tid >> 2;
        int rq = tid & 3;
        float4 z = ((const float4*)g_Z)[((size_t)o * M_TOTAL + row0 + m) * 4 + rq];
        Zt2[(rq * 4 + 0) * ZS2 + m] = pack2(z.x, z.x);
        Zt2[(rq * 4 + 1) * ZS2 + m] = pack2(z.y, z.y);
        Zt2[(rq * 4 + 2) * ZS2 + m] = pack2(z.z, z.z);
        Zt2[(rq * 4 + 3) * ZS2 + m] = pack2(z.w, z.w);
    }
    if (tid >= 128 && tid < 128 + ROWS_B) {
        int m = tid - 128;
        const float4* rp = (const float4*)(g_rsp + (size_t)(row0 + m) * (NB * NQ));
        float s = 1.0f;
        #pragma unroll
        for (int c = 0; c < 32; ++c) {
            float4 v = rp[c];
            s += (v.x + v.y) + (v.z + v.w);
        }
        rs[m] = s;
    }
    __syncthreads();

    const int mg = tid >> 5;        // 0..7 -> rows m0..m0+3
    const int qg = tid & 31;        // q = qg*4 and 128+qg*4
    const int m0 = mg * 4;

    const float4* b4 = (const float4*)bias;
    float4 ba = b4[o * 64 + qg];
    float4 bb = b4[o * 64 + 32 + qg];

    ulonglong2 Aa[4], Ab[4];
    #pragma unroll
    for (int j = 0; j < 4; ++j) {
        float r = rs[m0 + j];
        Aa[j].x = pack2(r * ba.x, r * ba.y);
        Aa[j].y = pack2(r * ba.z, r * ba.w);
        Ab[j].x = pack2(r * bb.x, r * bb.y);
        Ab[j].y = pack2(r * bb.z, r * bb.w);
    }

    #pragma unroll
    for (int r = 0; r < RANK; ++r) {
        const u64* zp = Zt2 + r * ZS2 + m0;
        ulonglong2 z01 = *(const ulonglong2*)(zp);       // broadcast LDS.128
        ulonglong2 z23 = *(const ulonglong2*)(zp + 2);
        u64 q0 = z01.x, q1 = z01.y, q2 = z23.x, q3 = z23.y;
        ulonglong2 ua = *(const ulonglong2*)(Us + r * 256 + qg * 4);
        ulonglong2 ub = *(const ulonglong2*)(Us + r * 256 + 128 + qg * 4);
        ffma2(Aa[0].x, q0, ua.x); ffma2(Aa[0].y, q0, ua.y);
        ffma2(Ab[0].x, q0, ub.x); ffma2(Ab[0].y, q0, ub.y);
        ffma2(Aa[1].x, q1, ua.x); ffma2(Aa[1].y, q1, ua.y);
        ffma2(Ab[1].x, q1, ub.x); ffma2(Ab[1].y, q1, ub.y);
        ffma2(Aa[2].x, q2, ua.x); ffma2(Aa[2].y, q2, ua.y);
        ffma2(Ab[2].x, q2, ub.x); ffma2(Ab[2].y, q2, ub.y);
        ffma2(Aa[3].x, q3, ua.x); ffma2(Aa[3].y, q3, ua.y);
        ffma2(Ab[3].x, q3, ub.x); ffma2(Ab[3].y, q3, ub.y);
    }

    size_t ob = (size_t)(row0 + m0) * OUT_DIM + o * 256 + qg * 4;
    #pragma unroll
    for (int j = 0; j < 4; ++j) {
        *(ulonglong2*)(out + ob + (size_t)j * OUT_DIM)       = Aa[j];
        *(ulonglong2*)(out + ob + (size_t)j * OUT_DIM + 128) = Ab[j];
    }
}

extern "C" void kernel_launch(void* const* d_in, const int* in_sizes, int n_in,
                              void* d_out, int out_size)
{
    const float* x    = (const float*)d_in[0];
    const float* S    = (const float*)d_in[1];
    const float* U    = (const float*)d_in[2];
    const float* Vt   = (const float*)d_in[3];
    const float* bias = (const float*)d_in[4];
    float* out = (float*)d_out;

    const int smA = (ROWS_A * XSTR) * (int)sizeof(float) + (KA / 2) * RANK * (int)sizeof(u64);
    cudaFuncSetAttribute(kernelA, cudaFuncAttributeMaxDynamicSharedMemorySize, smA);

    kernelA<<<dim3(NB * NQ, M_TOTAL / ROWS_A), 256, smA>>>(x, Vt);
    kernelZ<<<M_TOTAL / ROWS_Z, 256>>>(S);
    kernelB<<<dim3(NB, M_TOTAL / ROWS_B), 256>>>(U, bias, out);
}

// round 7
// speedup vs baseline: 1.0394x; 1.0394x over previous
#include <cuda_runtime.h>

#define M_TOTAL 2048
#define IN_DIM  4096
#define OUT_DIM 4096
#define NB      16
#define RANK    16
#define BLK     256
#define NQ      8      // split-K pieces in kernelA
#define KA      32     // p's per piece

typedef unsigned long long u64;

// Scratch (__device__ globals per allocation rules)
__device__ float g_T[NQ * M_TOTAL * NB * RANK];   // [qt][m][i][r]  16 MB (L2-resident)
__device__ float g_Z[NB * M_TOTAL * RANK];        // [o][m][r]      2 MB
__device__ float g_rsp[M_TOTAL * NB * NQ];        // [m][i*8+qt]    1 MB

// ---------- f32x2 packed helpers ----------
__device__ __forceinline__ u64 pack2(float lo, float hi) {
    u64 r; asm("mov.b64 %0, {%1, %2};" : "=l"(r) : "f"(lo), "f"(hi)); return r;
}
__device__ __forceinline__ void unpack2(u64 p, float& lo, float& hi) {
    asm("mov.b64 {%0, %1}, %2;" : "=f"(lo), "=f"(hi) : "l"(p));
}
__device__ __forceinline__ void ffma2(u64& d, u64 a, u64 b) {
    asm("fma.rn.f32x2 %0, %1, %2, %0;" : "+l"(d) : "l"(a), "l"(b));
}
__device__ __forceinline__ void fadd2(u64& d, u64 a) {
    asm("add.rn.f32x2 %0, %0, %1;" : "+l"(d) : "l"(a));
}

// ================= Kernel A: T_qt[m,i,r] = sum_{p in piece} x*Vt =================
// Thread tile: 2 rows x 8 ranks, f32x2 paired over p. 0.5 wf/FFMA2, no movs.
#define ROWS_A  256
#define XSTR    36     // 32 + 4 pad floats; LDS.128 conflict-free

__global__ void __launch_bounds__(256, 4)
kernelA(const float* __restrict__ x, const float* __restrict__ Vt)
{
    __shared__ float xs[ROWS_A * XSTR];        // 36.9 KB
    __shared__ u64   vts2[(KA / 2) * RANK];    // [p2][r] = (Vt[2p2][r],Vt[2p2+1][r]) 2 KB

    const int ib   = blockIdx.x >> 3;
    const int qt   = blockIdx.x & 7;
    const int row0 = blockIdx.y * ROWS_A;
    const int tid  = threadIdx.x;

    // Vt piece interleaved into p-pairs: thread -> (p2 = tid>>4, r = tid&15)
    {
        int p2 = tid >> 4, r = tid & 15;
        const float* vg = Vt + ((size_t)ib * BLK + qt * KA + 2 * p2) * RANK + r;
        vts2[p2 * 16 + r] = pack2(vg[0], vg[RANK]);
    }

    // x tile: 256 rows x 32 cols (8 float4 per thread)
    const float4* xg4 = (const float4*)x;
    #pragma unroll
    for (int idx = tid; idx < ROWS_A * 8; idx += 256) {
        int m  = idx >> 3;
        int c4 = idx & 7;
        ((float4*)(xs + m * XSTR))[c4] =
            xg4[(size_t)(row0 + m) * (IN_DIM / 4) + ib * 64 + qt * 8 + c4];
    }
    __syncthreads();

    const int mg = tid & 127;      // rows mg, mg+128
    const int rg = tid >> 7;       // 0/1 (warp-uniform) -> ranks r0..r0+7
    const int r0 = rg * 8;
    const float* xr0 = xs + mg * XSTR;
    const float* xr1 = xs + (mg + 128) * XSTR;

    u64 accA[8], accB[8];
    #pragma unroll
    for (int r = 0; r < 8; ++r) { accA[r] = 0ULL; accB[r] = 0ULL; }
    u64 rsA = 0ULL, rsB = 0ULL;

    #pragma unroll
    for (int p4 = 0; p4 < 8; ++p4) {
        ulonglong2 xa = *(const ulonglong2*)(xr0 + p4 * 4);   // (p0,p1),(p2,p3)
        ulonglong2 xb = *(const ulonglong2*)(xr1 + p4 * 4);
        if (rg == 0) {                       // warp-uniform: rowsum by rg==0 warps only
            fadd2(rsA, xa.x); fadd2(rsA, xa.y);
            fadd2(rsB, xb.x); fadd2(rsB, xb.y);
        }
        const u64* vp = vts2 + (2 * p4) * 16 + r0;
        {   // p2 = 2p4 (even pair)
            ulonglong2 v0 = *(const ulonglong2*)(vp);
            ulonglong2 v1 = *(const ulonglong2*)(vp + 2);
            ulonglong2 v2 = *(const ulonglong2*)(vp + 4);
            ulonglong2 v3 = *(const ulonglong2*)(vp + 6);
            ffma2(accA[0], xa.x, v0.x); ffma2(accA[1], xa.x, v0.y);
            ffma2(accA[2], xa.x, v1.x); ffma2(accA[3], xa.x, v1.y);
            ffma2(accA[4], xa.x, v2.x); ffma2(accA[5], xa.x, v2.y);
            ffma2(accA[6], xa.x, v3.x); ffma2(accA[7], xa.x, v3.y);
            ffma2(accB[0], xb.x, v0.x); ffma2(accB[1], xb.x, v0.y);
            ffma2(accB[2], xb.x, v1.x); ffma2(accB[3], xb.x, v1.y);
            ffma2(accB[4], xb.x, v2.x); ffma2(accB[5], xb.x, v2.y);
            ffma2(accB[6], xb.x, v3.x); ffma2(accB[7], xb.x, v3.y);
        }
        {   // p2 = 2p4+1 (odd pair)
            ulonglong2 v0 = *(const ulonglong2*)(vp + 16);
            ulonglong2 v1 = *(const ulonglong2*)(vp + 18);
            ulonglong2 v2 = *(const ulonglong2*)(vp + 20);
            ulonglong2 v3 = *(const ulonglong2*)(vp + 22);
            ffma2(accA[0], xa.y, v0.x); ffma2(accA[1], xa.y, v0.y);
            ffma2(accA[2], xa.y, v1.x); ffma2(accA[3], xa.y, v1.y);
            ffma2(accA[4], xa.y, v2.x); ffma2(accA[5], xa.y, v2.y);
            ffma2(accA[6], xa.y, v3.x); ffma2(accA[7], xa.y, v3.y);
            ffma2(accB[0], xb.y, v0.x); ffma2(accB[1], xb.y, v0.y);
            ffma2(accB[2], xb.y, v1.x); ffma2(accB[3], xb.y, v1.y);
            ffma2(accB[4], xb.y, v2.x); ffma2(accB[5], xb.y, v2.y);
            ffma2(accB[6], xb.y, v3.x); ffma2(accB[7], xb.y, v3.y);
        }
    }

    // Combine even/odd-p partials; store T ([qt][m][i][r])
    float* gTq = g_T + (size_t)qt * (M_TOTAL * NB * RANK);
    {
        float* dst = gTq + (size_t)(row0 + mg) * (NB * RANK) + ib * RANK + r0;
        float lo, hi; float4 t;
        unpack2(accA[0], lo, hi); t.x = lo + hi;
        unpack2(accA[1], lo, hi); t.y = lo + hi;
        unpack2(accA[2], lo, hi); t.z = lo + hi;
        unpack2(accA[3], lo, hi); t.w = lo + hi;
        *(float4*)(dst) = t;
        unpack2(accA[4], lo, hi); t.x = lo + hi;
        unpack2(accA[5], lo, hi); t.y = lo + hi;
        unpack2(accA[6], lo, hi); t.z = lo + hi;
        unpack2(accA[7], lo, hi); t.w = lo + hi;
        *(float4*)(dst + 4) = t;

        dst = gTq + (size_t)(row0 + mg + 128) * (NB * RANK) + ib * RANK + r0;
        unpack2(accB[0], lo, hi); t.x = lo + hi;
        unpack2(accB[1], lo, hi); t.y = lo + hi;
        unpack2(accB[2], lo, hi); t.z = lo + hi;
        unpack2(accB[3], lo, hi); t.w = lo + hi;
        *(float4*)(dst) = t;
        unpack2(accB[4], lo, hi); t.x = lo + hi;
        unpack2(accB[5], lo, hi); t.y = lo + hi;
        unpack2(accB[6], lo, hi); t.z = lo + hi;
        unpack2(accB[7], lo, hi); t.w = lo + hi;
        *(float4*)(dst + 4) = t;
    }

    if (rg == 0) {
        float lo, hi;
        unpack2(rsA, lo, hi);
        g_rsp[(size_t)(row0 + mg) * (NB * NQ) + ib * NQ + qt] = lo + hi;
        unpack2(rsB, lo, hi);
        g_rsp[(size_t)(row0 + mg + 128) * (NB * NQ) + ib * NQ + qt] = lo + hi;
    }
}

// ================= Kernel Z: Z[o][m][r] = sum_i T[m,i,r]*S[o,i,r] =================
#define ROWS_Z  8
#define TSTR    260

__global__ void __launch_bounds__(256)
kernelZ(const float* __restrict__ S)
{
    __shared__ float Ts[ROWS_Z * TSTR];    // 8.3 KB
    __shared__ float Ss[NB * NB * RANK];   // 16 KB

    const int row0 = blockIdx.x * ROWS_Z;
    const int tid  = threadIdx.x;

    #pragma unroll
    for (int i = tid; i < 1024; i += 256) ((float4*)Ss)[i] = ((const float4*)S)[i];

    // Sum 8 split-K pieces; contiguous per (qt,row)
    const float4* gT4 = (const float4*)g_T;
    const size_t  qs  = (size_t)M_TOTAL * 64;   // float4 per piece
    #pragma unroll
    for (int idx = tid; idx < ROWS_Z * 64; idx += 256) {
        int m  = idx >> 6;
        int c4 = idx & 63;
        size_t base = (size_t)(row0 + m) * 64 + c4;
        float4 a = gT4[base];
        #pragma unroll
        for (int q = 1; q < NQ; ++q) {
            float4 b = gT4[base + q * qs];
            a.x += b.x; a.y += b.y; a.z += b.z; a.w += b.w;
        }
        ((float4*)(Ts + m * TSTR))[c4] = a;
    }
    __syncthreads();

    const int m  = tid >> 5;          // 0..7
    const int r  = (tid >> 1) & 15;
    const int oh = tid & 1;           // o-half

    float t[NB];
    #pragma unroll
    for (int i = 0; i < NB; ++i) t[i] = Ts[m * TSTR + i * 16 + r];

    #pragma unroll
    for (int oo = 0; oo < 8; ++oo) {
        int o = oh * 8 + oo;
        float z = 0.f;
        #pragma unroll
        for (int i = 0; i < NB; ++i) z = fmaf(t[i], Ss[o * 256 + i * 16 + r], z);
        g_Z[((size_t)o * M_TOTAL + row0 + m) * RANK + r] = z;
    }
}

// ================= Kernel B: out = Z @ U + (1+rowsum)*bias =================
#define ROWS_B  32
#define ZS2     34      // u64 stride (even -> 16B-aligned ull2 loads)

__global__ void __launch_bounds__(256)
kernelB(const float* __restrict__ U, const float* __restrict__ bias,
        float* __restrict__ out)
{
    __shared__ float Us[RANK * BLK];       // 16 KB
    __shared__ u64   Zt2[RANK * ZS2];      // (z,z) duplicated pairs, [r][m]
    __shared__ float rs[ROWS_B];

    const int o    = blockIdx.x;
    const int row0 = blockIdx.y * ROWS_B;
    const int tid  = threadIdx.x;

    const float4* Ug4 = (const float4*)(U + (size_t)o * (RANK * BLK));
    #pragma unroll
    for (int i = tid; i < 1024; i += 256) ((float4*)Us)[i] = Ug4[i];

    if (tid < 128) {
        int m  = tid >> 2;
        int rq = tid & 3;
        float4 z = ((const float4*)g_Z)[((size_t)o * M_TOTAL + row0 + m) * 4 + rq];
        Zt2[(rq * 4 + 0) * ZS2 + m] = pack2(z.x, z.x);
        Zt2[(rq * 4 + 1) * ZS2 + m] = pack2(z.y, z.y);
        Zt2[(rq * 4 + 2) * ZS2 + m] = pack2(z.z, z.z);
        Zt2[(rq * 4 + 3) * ZS2 + m] = pack2(z.w, z.w);
    }
    if (tid >= 128 && tid < 128 + ROWS_B) {
        int m = tid - 128;
        const float4* rp = (const float4*)(g_rsp + (size_t)(row0 + m) * (NB * NQ));
        float s = 1.0f;
        #pragma unroll
        for (int c = 0; c < 32; ++c) {
            float4 v = rp[c];
            s += (v.x + v.y) + (v.z + v.w);
        }
        rs[m] = s;
    }
    __syncthreads();

    const int mg = tid >> 5;        // 0..7 -> rows m0..m0+3
    const int qg = tid & 31;        // q = qg*4 and 128+qg*4
    const int m0 = mg * 4;

    const float4* b4 = (const float4*)bias;
    float4 ba = b4[o * 64 + qg];
    float4 bb = b4[o * 64 + 32 + qg];

    ulonglong2 Aa[4], Ab[4];
    #pragma unroll
    for (int j = 0; j < 4; ++j) {
        float r = rs[m0 + j];
        Aa[j].x = pack2(r * ba.x, r * ba.y);
        Aa[j].y = pack2(r * ba.z, r * ba.w);
        Ab[j].x = pack2(r * bb.x, r * bb.y);
        Ab[j].y = pack2(r * bb.z, r * bb.w);
    }

    #pragma unroll
    for (int r = 0; r < RANK; ++r) {
        const u64* zp = Zt2 + r * ZS2 + m0;
        ulonglong2 z01 = *(const ulonglong2*)(zp);       // broadcast LDS.128
        ulonglong2 z23 = *(const ulonglong2*)(zp + 2);
        u64 q0 = z01.x, q1 = z01.y, q2 = z23.x, q3 = z23.y;
        ulonglong2 ua = *(const ulonglong2*)(Us + r * 256 + qg * 4);
        ulonglong2 ub = *(const ulonglong2*)(Us + r * 256 + 128 + qg * 4);
        ffma2(Aa[0].x, q0, ua.x); ffma2(Aa[0].y, q0, ua.y);
        ffma2(Ab[0].x, q0, ub.x); ffma2(Ab[0].y, q0, ub.y);
        ffma2(Aa[1].x, q1, ua.x); ffma2(Aa[1].y, q1, ua.y);
        ffma2(Ab[1].x, q1, ub.x); ffma2(Ab[1].y, q1, ub.y);
        ffma2(Aa[2].x, q2, ua.x); ffma2(Aa[2].y, q2, ua.y);
        ffma2(Ab[2].x, q2, ub.x); ffma2(Ab[2].y, q2, ub.y);
        ffma2(Aa[3].x, q3, ua.x); ffma2(Aa[3].y, q3, ua.y);
        ffma2(Ab[3].x, q3, ub.x); ffma2(Ab[3].y, q3, ub.y);
    }

    size_t ob = (size_t)(row0 + m0) * OUT_DIM + o * 256 + qg * 4;
    #pragma unroll
    for (int j = 0; j < 4; ++j) {
        *(ulonglong2*)(out + ob + (size_t)j * OUT_DIM)       = Aa[j];
        *(ulonglong2*)(out + ob + (size_t)j * OUT_DIM + 128) = Ab[j];
    }
}

extern "C" void kernel_launch(void* const* d_in, const int* in_sizes, int n_in,
                              void* d_out, int out_size)
{
    const float* x    = (const float*)d_in[0];
    const float* S    = (const float*)d_in[1];
    const float* U    = (const float*)d_in[2];
    const float* Vt   = (const float*)d_in[3];
    const float* bias = (const float*)d_in[4];
    float* out = (float*)d_out;

    kernelA<<<dim3(NB * NQ, M_TOTAL / ROWS_A), 256>>>(x, Vt);
    kernelZ<<<M_TOTAL / ROWS_Z, 256>>>(S);
    kernelB<<<dim3(NB, M_TOTAL / ROWS_B), 256>>>(U, bias, out);
}

// round 9
// speedup vs baseline: 1.2955x; 1.2464x over previous
#include <cuda_runtime.h>

#define M_TOTAL 2048
#define IN_DIM  4096
#define OUT_DIM 4096
#define NB      16
#define RANK    16
#define BLK     256

typedef unsigned long long u64;

// Scratch (__device__ globals per allocation rules)
__device__ float g_T[2 * NB * RANK * M_TOTAL];    // [h][ib][r][m]  4 MB, m contiguous
__device__ float g_Z[NB * RANK * M_TOTAL];        // [o][r][m]      2 MB, m contiguous
__device__ float g_rsp[M_TOTAL * NB * 2];         // [m][ib*2+h]    512 KB

// ---------- f32x2 packed helpers ----------
__device__ __forceinline__ u64 pack2(float lo, float hi) {
    u64 r; asm("mov.b64 %0, {%1, %2};" : "=l"(r) : "f"(lo), "f"(hi)); return r;
}
__device__ __forceinline__ void unpack2(u64 p, float& lo, float& hi) {
    asm("mov.b64 {%0, %1}, %2;" : "=f"(lo), "=f"(hi) : "l"(p));
}
__device__ __forceinline__ void ffma2(u64& d, u64 a, u64 b) {
    asm("fma.rn.f32x2 %0, %1, %2, %0;" : "+l"(d) : "l"(a), "l"(b));
}
__device__ __forceinline__ void fadd2(u64& d, u64 a) {
    asm("add.rn.f32x2 %0, %0, %1;" : "+l"(d) : "l"(a));
}

// ---------- cp.async helpers ----------
__device__ __forceinline__ unsigned smem_u32(const void* p) {
    unsigned a;
    asm("{ .reg .u64 t; cvta.to.shared.u64 t, %1; cvt.u32.u64 %0, t; }" : "=r"(a) : "l"(p));
    return a;
}
__device__ __forceinline__ void cp_async16(unsigned dst, const void* src) {
    asm volatile("cp.async.ca.shared.global [%0], [%1], 16;" :: "r"(dst), "l"(src));
}
__device__ __forceinline__ void cp_commit() {
    asm volatile("cp.async.commit_group;");
}
__device__ __forceinline__ void cp_wait1() {
    asm volatile("cp.async.wait_group 1;");
}
__device__ __forceinline__ void cp_wait0() {
    asm volatile("cp.async.wait_group 0;");
}

// ================= Kernel A =================
// Each CTA: 128 rows x one half-block (128 p's) as 4 sub-pieces of 32 p's,
// cp.async double-buffered, register accumulation across sub-pieces.
#define ROWS_A  128
#define PSTR    36            // 32 + 4 pad floats (144 B row, 16B-aligned)
#define NSP     4             // sub-pieces per CTA
#define KSP     32            // p's per sub-piece

__global__ void __launch_bounds__(256, 4)
kernelA(const float* __restrict__ x, const float* __restrict__ Vt)
{
    __shared__ float xs[2][ROWS_A * PSTR];        // 2 x 18 KB
    __shared__ u64   vts2[NSP * (KSP / 2) * RANK];// [sp][p2][r] 8 KB

    const int h    = blockIdx.x & 1;              // half-block (p 0..127 / 128..255)
    const int ib   = blockIdx.x >> 1;             // input block
    const int row0 = blockIdx.y * ROWS_A;
    const int tid  = threadIdx.x;

    // Stage all Vt pairs for this half-block: vts2[sp][p2][r] = (Vt[p],Vt[p+1]) at rank r
    {
        int p2l = tid >> 4, r = tid & 15;
        #pragma unroll
        for (int sp = 0; sp < NSP; ++sp) {
            const float* vg = Vt + ((size_t)ib * BLK + h * 128 + sp * KSP + 2 * p2l) * RANK + r;
            vts2[sp * 256 + p2l * 16 + r] = pack2(vg[0], vg[RANK]);
        }
    }

    // cp.async fill of sub-piece sp into buffer sp&1
    const float4* xg4 = (const float4*)x;
    unsigned xs_base0 = smem_u32(&xs[0][0]);
    unsigned xs_base1 = smem_u32(&xs[1][0]);
    auto fill = [&](int sp) {
        unsigned base = (sp & 1) ? xs_base1 : xs_base0;
        #pragma unroll
        for (int k = 0; k < 4; ++k) {
            int idx = tid + k * 256;          // 0..1023
            int m   = idx >> 3;
            int c4  = idx & 7;
            const float4* src = xg4 + ((size_t)(row0 + m) * (IN_DIM / 4)
                                       + ib * 64 + h * 32 + sp * 8 + c4);
            cp_async16(base + (m * PSTR + c4 * 4) * 4, src);
        }
        cp_commit();
    };

    fill(0);
    fill(1);

    const int mg = tid & 127;       // row
    const int rg = tid >> 7;        // 0/1 -> ranks rg*8..rg*8+7 (warp-uniform)
    const int r0 = rg * 8;

    u64 acc[8];
    #pragma unroll
    for (int k = 0; k < 8; ++k) acc[k] = 0ULL;
    u64 rs = 0ULL;

    #pragma unroll
    for (int sp = 0; sp < NSP; ++sp) {
        if (sp < NSP - 1) cp_wait1();   // sub-piece sp's group complete
        else              cp_wait0();   // FINAL piece: drain everything (R8 bug fix)
        __syncthreads();
        const float* xr = &xs[sp & 1][mg * PSTR];
        const u64*   vb = vts2 + sp * 256 + r0;

        #pragma unroll
        for (int p4 = 0; p4 < 8; ++p4) {
            ulonglong2 xa = *(const ulonglong2*)(xr + p4 * 4);   // (p0,p1),(p2,p3)
            if (rg == 0) { fadd2(rs, xa.x); fadd2(rs, xa.y); }
            const u64* v0 = vb + (2 * p4) * 16;
            {
                ulonglong2 a = *(const ulonglong2*)(v0);
                ulonglong2 b = *(const ulonglong2*)(v0 + 2);
                ulonglong2 c = *(const ulonglong2*)(v0 + 4);
                ulonglong2 d = *(const ulonglong2*)(v0 + 6);
                ffma2(acc[0], xa.x, a.x); ffma2(acc[1], xa.x, a.y);
                ffma2(acc[2], xa.x, b.x); ffma2(acc[3], xa.x, b.y);
                ffma2(acc[4], xa.x, c.x); ffma2(acc[5], xa.x, c.y);
                ffma2(acc[6], xa.x, d.x); ffma2(acc[7], xa.x, d.y);
            }
            const u64* v1 = v0 + 16;
            {
                ulonglong2 a = *(const ulonglong2*)(v1);
                ulonglong2 b = *(const ulonglong2*)(v1 + 2);
                ulonglong2 c = *(const ulonglong2*)(v1 + 4);
                ulonglong2 d = *(const ulonglong2*)(v1 + 6);
                ffma2(acc[0], xa.y, a.x); ffma2(acc[1], xa.y, a.y);
                ffma2(acc[2], xa.y, b.x); ffma2(acc[3], xa.y, b.y);
                ffma2(acc[4], xa.y, c.x); ffma2(acc[5], xa.y, c.y);
                ffma2(acc[6], xa.y, d.x); ffma2(acc[7], xa.y, d.y);
            }
        }
        __syncthreads();            // all warps done with this buffer
        if (sp + 2 < NSP) fill(sp + 2);
    }

    // Store T: layout [h][ib][r][m] -> fully coalesced STG.32 per rank
    {
        float* base = g_T + ((size_t)(h * NB + ib) * RANK) * M_TOTAL + row0 + mg;
        #pragma unroll
        for (int k = 0; k < 8; ++k) {
            float lo, hi;
            unpack2(acc[k], lo, hi);
            base[(size_t)(r0 + k) * M_TOTAL] = lo + hi;
        }
    }
    if (rg == 0) {
        float lo, hi;
        unpack2(rs, lo, hi);
        g_rsp[(size_t)(row0 + mg) * (NB * 2) + ib * 2 + h] = lo + hi;
    }
}

// ================= Kernel Z =================
// For each rank r: Z_r[o][m] = sum_i S[o][i][r] * (T0+T1)[i][r][m]
// grid (16 r, 8 m-chunks of 256). All loads/stores m-contiguous.
__global__ void __launch_bounds__(256)
kernelZ(const float* __restrict__ S)
{
    __shared__ float Ts[NB * 256];     // [i][m] 16 KB
    __shared__ float Ss[NB * NB];      // S[o][i] at this r

    const int r   = blockIdx.x;
    const int m0  = blockIdx.y * 256;
    const int tid = threadIdx.x;

    Ss[tid] = S[tid * RANK + r];       // tid = o*16+i

    const float4* gT4 = (const float4*)g_T;
    #pragma unroll
    for (int k = 0; k < 4; ++k) {
        int idx = tid + k * 256;       // 0..1023 over i(16) x c4(64)
        int i   = idx >> 6;
        int c4  = idx & 63;
        size_t i0 = ((size_t)(0 * NB + i) * RANK + r) * (M_TOTAL / 4) + (m0 / 4) + c4;
        size_t i1 = ((size_t)(1 * NB + i) * RANK + r) * (M_TOTAL / 4) + (m0 / 4) + c4;
        float4 a = gT4[i0];
        float4 b = gT4[i1];
        a.x += b.x; a.y += b.y; a.z += b.z; a.w += b.w;
        ((float4*)(Ts + i * 256))[c4] = a;
    }
    __syncthreads();

    float t[NB];
    #pragma unroll
    for (int i = 0; i < NB; ++i) t[i] = Ts[i * 256 + tid];   // conflict-free

    #pragma unroll 4
    for (int o = 0; o < NB; ++o) {
        float z = 0.f;
        #pragma unroll
        for (int i = 0; i < NB; ++i) z = fmaf(t[i], Ss[o * 16 + i], z);
        g_Z[((size_t)(o * RANK + r)) * M_TOTAL + m0 + tid] = z;   // coalesced
    }
}

// ================= Kernel B: out = Z @ U + (1+rowsum)*bias =================
#define ROWS_B  32
#define ZS2     34      // u64 stride (even -> 16B-aligned ull2 loads)

__global__ void __launch_bounds__(256)
kernelB(const float* __restrict__ U, const float* __restrict__ bias,
        float* __restrict__ out)
{
    __shared__ float Us[RANK * BLK];       // 16 KB
    __shared__ u64   Zt2[RANK * ZS2];      // (z,z) duplicated pairs, [r][m]
    __shared__ float rs[ROWS_B];

    const int o    = blockIdx.x;
    const int row0 = blockIdx.y * ROWS_B;
    const int tid  = threadIdx.x;

    const float4* Ug4 = (const float4*)(U + (size_t)o * (RANK * BLK));
    #pragma unroll
    for (int i = tid; i < 1024; i += 256) ((float4*)Us)[i] = Ug4[i];

    // Zt2 fill from g_Z[o][r][m] (m-contiguous)
    {
        int r = tid >> 5;         // 0..7
        int m = tid & 31;
        float z0 = g_Z[((size_t)(o * RANK + r))     * M_TOTAL + row0 + m];
        float z1 = g_Z[((size_t)(o * RANK + r + 8)) * M_TOTAL + row0 + m];
        Zt2[r * ZS2 + m]       = pack2(z0, z0);
        Zt2[(r + 8) * ZS2 + m] = pack2(z1, z1);
    }
    if (tid < ROWS_B) {
        const float4* rp = (const float4*)(g_rsp + (size_t)(row0 + tid) * (NB * 2));
        float s = 1.0f;
        #pragma unroll
        for (int c = 0; c < 8; ++c) {
            float4 v = rp[c];
            s += (v.x + v.y) + (v.z + v.w);
        }
        rs[tid] = s;
    }
    __syncthreads();

    const int mg = tid >> 5;        // 0..7 -> rows m0..m0+3
    const int qg = tid & 31;        // q = qg*4 and 128+qg*4
    const int m0 = mg * 4;

    const float4* b4 = (const float4*)bias;
    float4 ba = b4[o * 64 + qg];
    float4 bb = b4[o * 64 + 32 + qg];

    ulonglong2 Aa[4], Ab[4];
    #pragma unroll
    for (int j = 0; j < 4; ++j) {
        float r = rs[m0 + j];
        Aa[j].x = pack2(r * ba.x, r * ba.y);
        Aa[j].y = pack2(r * ba.z, r * ba.w);
        Ab[j].x = pack2(r * bb.x, r * bb.y);
        Ab[j].y = pack2(r * bb.z, r * bb.w);
    }

    #pragma unroll
    for (int r = 0; r < RANK; ++r) {
        const u64* zp = Zt2 + r * ZS2 + m0;
        ulonglong2 z01 = *(const ulonglong2*)(zp);       // broadcast LDS.128
        ulonglong2 z23 = *(const ulonglong2*)(zp + 2);
        u64 q0 = z01.x, q1 = z01.y, q2 = z23.x, q3 = z23.y;
        ulonglong2 ua = *(const ulonglong2*)(Us + r * 256 + qg * 4);
        ulonglong2 ub = *(const ulonglong2*)(Us + r * 256 + 128 + qg * 4);
        ffma2(Aa[0].x, q0, ua.x); ffma2(Aa[0].y, q0, ua.y);
        ffma2(Ab[0].x, q0, ub.x); ffma2(Ab[0].y, q0, ub.y);
        ffma2(Aa[1].x, q1, ua.x); ffma2(Aa[1].y, q1, ua.y);
        ffma2(Ab[1].x, q1, ub.x); ffma2(Ab[1].y, q1, ub.y);
        ffma2(Aa[2].x, q2, ua.x); ffma2(Aa[2].y, q2, ua.y);
        ffma2(Ab[2].x, q2, ub.x); ffma2(Ab[2].y, q2, ub.y);
        ffma2(Aa[3].x, q3, ua.x); ffma2(Aa[3].y, q3, ua.y);
        ffma2(Ab[3].x, q3, ub.x); ffma2(Ab[3].y, q3, ub.y);
    }

    size_t ob = (size_t)(row0 + m0) * OUT_DIM + o * 256 + qg * 4;
    #pragma unroll
    for (int j = 0; j < 4; ++j) {
        *(ulonglong2*)(out + ob + (size_t)j * OUT_DIM)       = Aa[j];
        *(ulonglong2*)(out + ob + (size_t)j * OUT_DIM + 128) = Ab[j];
    }
}

extern "C" void kernel_launch(void* const* d_in, const int* in_sizes, int n_in,
                              void* d_out, int out_size)
{
    const float* x    = (const float*)d_in[0];
    const float* S    = (const float*)d_in[1];
    const float* U    = (const float*)d_in[2];
    const float* Vt   = (const float*)d_in[3];
    const float* bias = (const float*)d_in[4];
    float* out = (float*)d_out;

    kernelA<<<dim3(NB * 2, M_TOTAL / ROWS_A), 256>>>(x, Vt);
    kernelZ<<<dim3(RANK, M_TOTAL / 256), 256>>>(S);
    kernelB<<<dim3(NB, M_TOTAL / ROWS_B), 256>>>(U, bias, out);
}